// round 6
// baseline (speedup 1.0000x reference)
#include <cuda_runtime.h>
#include <math.h>

#define HGT   64
#define WID   64
#define CH    256
#define BATCH 4
#define HW    (HGT*WID)
#define RAD   3
#define NK    49
#define PXB   32          // pixels per logits block (half row)
#define NCB   (PXB+6)     // 38 neighborhood columns
#define X2ROWS (7*NCB)    // 266
#define CHUNK 16
#define STR   20          // smem row stride (floats) for 16-ch chunk
#define WSTR  52

// Pixel-major scratch: [B][HW][C]
__device__ float g_q[BATCH*HW*CH];
__device__ float g_k[BATCH*HW*CH];
__device__ float g_v[BATCH*HW*CH];
// softmax weights: [512 blocks][32 px][52]
__device__ float g_w[BATCH*HGT*2*PXB*WSTR];

// ---------------- f32x2 packed helpers ----------------
__device__ __forceinline__ void fma2(unsigned long long& d,
                                     unsigned long long a,
                                     unsigned long long b) {
    asm("fma.rn.f32x2 %0, %1, %2, %0;" : "+l"(d) : "l"(a), "l"(b));
}
__device__ __forceinline__ unsigned long long dup2(float v) {
    unsigned long long d; unsigned r = __float_as_uint(v);
    asm("mov.b64 %0, {%1, %2};" : "=l"(d) : "r"(r), "r"(r));
    return d;
}
__device__ __forceinline__ float2 unpk(unsigned long long v) {
    unsigned lo, hi;
    asm("mov.b64 {%0, %1}, %2;" : "=r"(lo), "=r"(hi) : "l"(v));
    return make_float2(__uint_as_float(lo), __uint_as_float(hi));
}

// ---------------------------------------------------------------------------
// GEMM: Yt[b][p][o] = sum_c X[b][c][p] * W[o][c]
// 128x128 tile, BK=8, double-buffered smem, FFMA2 inner (8x8 microtile,
// split 4+4 offsets for conflict-free LDS.128).
// ---------------------------------------------------------------------------
__global__ __launch_bounds__(256) void gemm_kernel(
    const float* __restrict__ x,
    const float* __restrict__ w1,
    const float* __restrict__ w2,
    const float* __restrict__ w3)
{
    const int z    = blockIdx.z;
    const int b    = z / 3;
    const int wsel = z - b*3;
    const float* W = (wsel == 0) ? w1 : (wsel == 1 ? w2 : w3);
    float* Y = ((wsel == 0) ? g_q : (wsel == 1 ? g_k : g_v)) + (size_t)b * HW * CH;
    const float* X = x + (size_t)b * CH * HW;

    const int p0 = blockIdx.x * 128;
    const int o0 = blockIdx.y * 128;

    __shared__ float As[2][8][128];
    __shared__ float Bs[2][8][128];

    const int tid = threadIdx.x;
    const int tx  = tid & 15;
    const int ty  = tid >> 4;

    const int a_cr = tid >> 5;          // 0..7
    const int a_p4 = (tid & 31) << 2;   // 0..124
    const int b_o  = tid >> 1;          // 0..127
    const int b_c4 = (tid & 1) << 2;    // 0 or 4

    const float* Xa = X + (size_t)a_cr * HW + p0 + a_p4;
    const float* Wb = W + (size_t)(o0 + b_o) * CH + b_c4;

    float4 ra = *(const float4*)Xa;
    float4 rb = *(const float4*)Wb;
    *(float4*)(&As[0][a_cr][a_p4]) = ra;
    Bs[0][b_c4 + 0][b_o] = rb.x;
    Bs[0][b_c4 + 1][b_o] = rb.y;
    Bs[0][b_c4 + 2][b_o] = rb.z;
    Bs[0][b_c4 + 3][b_o] = rb.w;
    __syncthreads();

    unsigned long long acc2[4][8];
#pragma unroll
    for (int i = 0; i < 4; i++)
#pragma unroll
        for (int j = 0; j < 8; j++) acc2[i][j] = 0ULL;

#pragma unroll 2
    for (int kt = 0; kt < 32; kt++) {
        const int cur = kt & 1;
        if (kt < 31) {
            ra = *(const float4*)(Xa + (size_t)(kt + 1) * 8 * HW);
            rb = *(const float4*)(Wb + (kt + 1) * 8);
        }
#pragma unroll
        for (int k = 0; k < 8; k++) {
            ulonglong2 a01 = *(const ulonglong2*)(&As[cur][k][ty * 4]);
            ulonglong2 a23 = *(const ulonglong2*)(&As[cur][k][64 + ty * 4]);
            float4 bv0 = *(const float4*)(&Bs[cur][k][tx * 4]);
            float4 bv1 = *(const float4*)(&Bs[cur][k][64 + tx * 4]);
            unsigned long long av[4] = { a01.x, a01.y, a23.x, a23.y };
            unsigned long long bd[8];
            bd[0] = dup2(bv0.x); bd[1] = dup2(bv0.y);
            bd[2] = dup2(bv0.z); bd[3] = dup2(bv0.w);
            bd[4] = dup2(bv1.x); bd[5] = dup2(bv1.y);
            bd[6] = dup2(bv1.z); bd[7] = dup2(bv1.w);
#pragma unroll
            for (int i2 = 0; i2 < 4; i2++)
#pragma unroll
                for (int j = 0; j < 8; j++)
                    fma2(acc2[i2][j], av[i2], bd[j]);
        }
        if (kt < 31) {
            const int nxt = cur ^ 1;
            *(float4*)(&As[nxt][a_cr][a_p4]) = ra;
            Bs[nxt][b_c4 + 0][b_o] = rb.x;
            Bs[nxt][b_c4 + 1][b_o] = rb.y;
            Bs[nxt][b_c4 + 2][b_o] = rb.z;
            Bs[nxt][b_c4 + 3][b_o] = rb.w;
            __syncthreads();
        }
    }

    // epilogue: each acc2 pair covers two consecutive p rows
#pragma unroll
    for (int i2 = 0; i2 < 4; i2++) {
        const int prow = p0 + ((i2 < 2) ? (ty * 4 + 2 * i2)
                                        : (64 + ty * 4 + 2 * (i2 - 2)));
        float lo[8], hi[8];
#pragma unroll
        for (int j = 0; j < 8; j++) {
            float2 t = unpk(acc2[i2][j]);
            lo[j] = t.x; hi[j] = t.y;
        }
        float* yl = Y + (size_t)prow * CH + o0;
        *(float4*)(yl + tx * 4)      = make_float4(lo[0], lo[1], lo[2], lo[3]);
        *(float4*)(yl + 64 + tx * 4) = make_float4(lo[4], lo[5], lo[6], lo[7]);
        float* yh = yl + CH;
        *(float4*)(yh + tx * 4)      = make_float4(hi[0], hi[1], hi[2], hi[3]);
        *(float4*)(yh + 64 + tx * 4) = make_float4(hi[4], hi[5], hi[6], hi[7]);
    }
}

// ---------------------------------------------------------------------------
// Logits + softmax: block = (b, h, half-row of 32 px). 256 threads, 30.5KB.
// FFMA2 inner loop; writes softmax weights to g_w.
// ---------------------------------------------------------------------------
#define WS_OFF   0
#define X1_OFF   1664
#define X2_OFF   (1664 + PXB*STR)       // 2304
#define SMEM_FLOATS (1664 + PXB*STR + X2ROWS*STR)   // 7624
#define NUNITS   (PXB*4 + X2ROWS*4)     // 1192 float4 staging units per chunk

__global__ __launch_bounds__(256) void attn_logits(void)
{
    __shared__ float smem[SMEM_FLOATS];
    float* ws = smem + WS_OFF;

    const int blk  = blockIdx.x;          // b*128 + h*2 + half
    const int b    = blk >> 7;
    const int h    = (blk >> 1) & 63;
    const int half = blk & 1;
    const int px0  = half * PXB;
    const int tid  = threadIdx.x;

    const int px   = tid >> 3;            // 0..31
    const int part = tid & 7;             // 0..7

    const size_t bbase = (size_t)b * HW;

    // staging plan: 5 float4 units per thread, computed once
    const float* gp[5];
    int so[5];
#pragma unroll
    for (int it = 0; it < 5; it++) {
        int unit = tid + it * 256;
        gp[it] = 0; so[it] = -1;
        if (unit < PXB * 4) {
            int p  = unit >> 2;
            int c4 = (unit & 3) << 2;
            gp[it] = g_q + (bbase + (size_t)h * WID + px0 + p) * CH + c4;
            so[it] = X1_OFF + p * STR + c4;
        } else if (unit < NUNITS) {
            int u   = unit - PXB * 4;
            int row = u >> 2;
            int c4  = (u & 3) << 2;
            int dh  = row / NCB;
            int col = row - dh * NCB;
            int hh  = h + dh - RAD;
            int gw  = px0 + col - RAD;
            so[it] = X2_OFF + row * STR + c4;
            if (hh >= 0 && hh < HGT && gw >= 0 && gw < WID)
                gp[it] = g_k + (bbase + (size_t)hh * WID + gw) * CH + c4;
        }
    }

    unsigned long long acc2[7];
    int nbrow[7];
#pragma unroll
    for (int j = 0; j < 7; j++) {
        acc2[j] = 0ULL;
        int k  = part + 8 * j;
        int kk = (k < NK) ? k : 0;
        int dh = kk / 7, dw = kk - dh * 7;
        nbrow[j] = X2_OFF + (dh * NCB + px + dw) * STR;
    }

    // prologue: chunk 0 into registers
    float4 rg[5];
#pragma unroll
    for (int it = 0; it < 5; it++) {
        rg[it] = make_float4(0.f, 0.f, 0.f, 0.f);
        if (so[it] >= 0 && gp[it]) rg[it] = *(const float4*)(gp[it]);
    }

    const float* x1p = smem + X1_OFF + px * STR;

    for (int ch = 0; ch < CH / CHUNK; ch++) {
#pragma unroll
        for (int it = 0; it < 5; it++)
            if (so[it] >= 0) *(float4*)(smem + so[it]) = rg[it];
        __syncthreads();

        if (ch + 1 < CH / CHUNK) {
            int cco = (ch + 1) * CHUNK;
#pragma unroll
            for (int it = 0; it < 5; it++) {
                rg[it] = make_float4(0.f, 0.f, 0.f, 0.f);
                if (so[it] >= 0 && gp[it]) rg[it] = *(const float4*)(gp[it] + cco);
            }
        }

#pragma unroll
        for (int c4 = 0; c4 < CHUNK; c4 += 4) {
            ulonglong2 q2 = *(const ulonglong2*)(x1p + c4);
#pragma unroll
            for (int j = 0; j < 7; j++) {
                ulonglong2 k2 = *(const ulonglong2*)(smem + nbrow[j] + c4);
                fma2(acc2[j], q2.x, k2.x);
                fma2(acc2[j], q2.y, k2.y);
            }
        }
        __syncthreads();
    }

    float acc[7];
#pragma unroll
    for (int j = 0; j < 7; j++) {
        float2 t = unpk(acc2[j]);
        acc[j] = t.x + t.y;
    }

    // softmax across the 8-thread group owning pixel px
    float m = -1e30f;
#pragma unroll
    for (int j = 0; j < 7; j++)
        if (part + 8 * j < NK) m = fmaxf(m, acc[j]);
    m = fmaxf(m, __shfl_xor_sync(0xffffffffu, m, 1));
    m = fmaxf(m, __shfl_xor_sync(0xffffffffu, m, 2));
    m = fmaxf(m, __shfl_xor_sync(0xffffffffu, m, 4));

    float e[7];
    float s = 0.f;
#pragma unroll
    for (int j = 0; j < 7; j++) {
        int k = part + 8 * j;
        e[j] = (k < NK) ? __expf(acc[j] - m) : 0.f;
        s += e[j];
    }
    s += __shfl_xor_sync(0xffffffffu, s, 1);
    s += __shfl_xor_sync(0xffffffffu, s, 2);
    s += __shfl_xor_sync(0xffffffffu, s, 4);
    float inv = 1.f / s;
#pragma unroll
    for (int j = 0; j < 7; j++) {
        int k = part + 8 * j;
        if (k < NK) ws[px * WSTR + k] = e[j] * inv;
    }
    __syncthreads();

    // coalesced dump of weights to global
    float* gwo = g_w + (size_t)blk * (PXB * WSTR);
    for (int i = tid; i < (PXB * WSTR) / 4; i += 256)
        *(float4*)(gwo + i * 4) = *(const float4*)(ws + i * 4);
}

// ---------------------------------------------------------------------------
// Aggregation: block = (b, h). 256 threads, thread = channel.
// 4 passes of 16 px; weights broadcast from smem; float4 stores from regs.
// ---------------------------------------------------------------------------
__global__ __launch_bounds__(256) void attn_agg(float* __restrict__ out)
{
    __shared__ float wsm[64 * WSTR];    // 3328 floats

    const int blk = blockIdx.x;         // b*64 + h
    const int b   = blk >> 6;
    const int h   = blk & 63;
    const int tid = threadIdx.x;

    const float* gwi = g_w + (size_t)(b * 128 + h * 2) * (PXB * WSTR);
    for (int i = tid; i < (64 * WSTR) / 4; i += 256)
        *(float4*)(wsm + i * 4) = *(const float4*)(gwi + i * 4);
    __syncthreads();

    const int c = tid;
    const size_t bbase = (size_t)b * HW;

#pragma unroll 1
    for (int hv = 0; hv < 4; hv++) {
        const int p0h = hv * 16;
        float oacc[16];
#pragma unroll
        for (int i = 0; i < 16; i++) oacc[i] = 0.f;

        for (int dh = 0; dh < 7; dh++) {
            int hh = h + dh - RAD;
            if (hh < 0 || hh >= HGT) continue;          // uniform branch
            const float* vrow = g_v + (bbase + (size_t)hh * WID) * CH + c;
            const float* wsp  = wsm + p0h * WSTR + dh * 7;
#pragma unroll
            for (int wg = 0; wg < 22; wg++) {           // 16 + 6 cols
                int gw2 = p0h + wg - RAD;
                float vv = (gw2 >= 0 && gw2 < WID) ? vrow[(size_t)gw2 * CH] : 0.f;
#pragma unroll
                for (int dw = 0; dw < 7; dw++) {
                    int pl = wg - dw;                   // compile-time per iter
                    if (pl >= 0 && pl < 16)
                        oacc[pl] = fmaf(wsp[pl * WSTR + dw], vv, oacc[pl]);
                }
            }
        }

        float* op = out + ((size_t)(b * CH + c) * HGT + h) * WID + p0h;
        *(float4*)(op +  0) = make_float4(oacc[0],  oacc[1],  oacc[2],  oacc[3]);
        *(float4*)(op +  4) = make_float4(oacc[4],  oacc[5],  oacc[6],  oacc[7]);
        *(float4*)(op +  8) = make_float4(oacc[8],  oacc[9],  oacc[10], oacc[11]);
        *(float4*)(op + 12) = make_float4(oacc[12], oacc[13], oacc[14], oacc[15]);
    }
}

// ---------------------------------------------------------------------------
extern "C" void kernel_launch(void* const* d_in, const int* in_sizes, int n_in,
                              void* d_out, int out_size)
{
    const float* x  = (const float*)d_in[0];
    const float* w1 = (const float*)d_in[1];
    const float* w2 = (const float*)d_in[2];
    const float* w3 = (const float*)d_in[3];
    float* out = (float*)d_out;
    (void)in_sizes; (void)n_in; (void)out_size;

    dim3 ggrid(HW / 128, CH / 128, BATCH * 3);
    gemm_kernel<<<ggrid, 256>>>(x, w1, w2, w3);

    attn_logits<<<BATCH * HGT * 2, 256>>>();
    attn_agg<<<BATCH * HGT, 256>>>(out);
}